// round 15
// baseline (speedup 1.0000x reference)
#include <cuda_runtime.h>
#include <cuda_bf16.h>
#include <cuda_fp16.h>
#include <cstdint>
#include <cstddef>

#define DEVI __device__ __forceinline__
#define LOG2E 1.4426950408889634f
#define NCTA 304                     // 152 SMs x 2 CTAs

// ------------------------------------------------------------------
// Scratch (__device__ globals; allocation-free rule)
// ------------------------------------------------------------------
__device__ int g_tickP, g_tickA;
__device__ int g_cnt[768];                         // per-(qt,h,bb) branch-finish counters
__device__ float g_part[3][8ull * 1024 * 768];     // per-branch attention partials
__device__ __half g_x16[3ull * 8192 * 768];        // fp16 branch-scaled x (all GEMMs)
__device__ __half g_Wh[9ull * 768 * 768];          // W hi (fp16); mats 6-8: only plane
__device__ __half g_Wl[9ull * 768 * 768];          // W lo (fp16 residual); mats 0-5
// attention inputs: fp16. Q,K as hi+lo split; V single plane.
__device__ __half g_Qh[3ull * 8 * 12 * 1024 * 64]; // Q pre-scaled by log2(e)
__device__ __half g_Ql[3ull * 8 * 12 * 1024 * 64];
__device__ __half g_Kh[3ull * 8 * 12 * 1024 * 64];
__device__ __half g_Kl[3ull * 8 * 12 * 1024 * 64];
__device__ __half g_V [3ull * 8 * 12 * 1024 * 64];

// ------------------------------------------------------------------
// Helpers
// ------------------------------------------------------------------
DEVI uint32_t smaddr(const void* p) { return (uint32_t)__cvta_generic_to_shared(p); }

DEVI uint32_t packf16(float a, float b) {
    __half2 h = __floats2half2_rn(a, b);
    uint32_t u; memcpy(&u, &h, 4); return u;
}
DEVI uint32_t packf16l(float a, float b, uint32_t hbits) {
    __half2 h; memcpy(&h, &hbits, 4);
    float2 f = __half22float2(h);
    return packf16(a - f.x, b - f.y);
}
DEVI float ex2(float x) { float r; asm("ex2.approx.f32 %0, %1;" : "=f"(r) : "f"(x)); return r; }

DEVI void cp16(uint32_t dst, const void* src) {
    asm volatile("cp.async.cg.shared.global [%0], [%1], 16;" :: "r"(dst), "l"(src) : "memory");
}
DEVI void cp_commit() { asm volatile("cp.async.commit_group;" ::: "memory"); }
DEVI void cp_wait0()  { asm volatile("cp.async.wait_group 0;" ::: "memory"); }

DEVI void ldsm4(uint32_t r[4], uint32_t a) {
    asm volatile("ldmatrix.sync.aligned.m8n8.x4.shared.b16 {%0,%1,%2,%3}, [%4];"
                 : "=r"(r[0]), "=r"(r[1]), "=r"(r[2]), "=r"(r[3]) : "r"(a));
}
DEVI void ldsm4t(uint32_t r[4], uint32_t a) {
    asm volatile("ldmatrix.sync.aligned.m8n8.x4.trans.shared.b16 {%0,%1,%2,%3}, [%4];"
                 : "=r"(r[0]), "=r"(r[1]), "=r"(r[2]), "=r"(r[3]) : "r"(a));
}
DEVI void mma16h(float d[4], const uint32_t a[4], const uint32_t b[2]) {
    asm volatile(
        "mma.sync.aligned.m16n8k16.row.col.f32.f16.f16.f32 "
        "{%0,%1,%2,%3}, {%4,%5,%6,%7}, {%8,%9}, {%0,%1,%2,%3};"
        : "+f"(d[0]), "+f"(d[1]), "+f"(d[2]), "+f"(d[3])
        : "r"(a[0]), "r"(a[1]), "r"(a[2]), "r"(a[3]), "r"(b[0]), "r"(b[1]));
}

// ------------------------------------------------------------------
// Kernel 1: fused row scalars + branch-scaled fp16 x.
// Resets tickets and branch-finish counters (graph replay safe).
// ------------------------------------------------------------------
__global__ __launch_bounds__(192) void prep_x_fused(const float* __restrict__ x) {
    __shared__ float red[6];
    __shared__ float sbr[2];
    const int row = blockIdx.x, tid = threadIdx.x;
    if (row == 0 && tid == 0) { g_tickP = 0; g_tickA = 0; }
    if (row < 4) g_cnt[row * 192 + tid] = 0;

    float4 v = *(const float4*)&x[(size_t)row * 768 + tid * 4];
    float ss = fmaf(v.x, v.x, fmaf(v.y, v.y, fmaf(v.z, v.z, v.w * v.w)));
#pragma unroll
    for (int o = 16; o; o >>= 1) ss += __shfl_xor_sync(0xffffffffu, ss, o);
    if ((tid & 31) == 0) red[tid >> 5] = ss;
    __syncthreads();
    if (tid == 0) {
        float t = 0.f;
#pragma unroll
        for (int i = 0; i < 6; ++i) t += red[i];
        float n = fmaxf(sqrtf(t), 1e-5f);
        const float sc = 0.316227766016837933f;     // sqrt(0.1)
        float a = sc * n;
        float th = tanhf(a);
        float s_pre = th / a;
        float norm_h = th / sc;
        float maxn = (1.0f - 4e-3f) / sc;
        sbr[0] = (norm_h > maxn) ? s_pre * (maxn / norm_h) : s_pre;
        float arg = fminf(a, 1.0f - 1e-5f);
        float art = 0.5f * logf((1.0f + arg) / (1.0f - arg));
        sbr[1] = art / (n * sc);
    }
    __syncthreads();
    {
        const int c = tid * 4;
#pragma unroll
        for (int br = 0; br < 3; ++br) {
            float s = (br == 0) ? 1.0f : sbr[br - 1];
            size_t o = ((size_t)br * 8192 + row) * 768 + c;
            *(uint32_t*)&g_x16[o]     = packf16(v.x * s, v.y * s);
            *(uint32_t*)&g_x16[o + 2] = packf16(v.z * s, v.w * s);
        }
    }
}

// ------------------------------------------------------------------
// Kernel 1c: split weights into fp16 hi(+lo) planes.
// ------------------------------------------------------------------
__global__ __launch_bounds__(192) void prep_w(
    const float* __restrict__ wq, const float* __restrict__ wk, const float* __restrict__ wv) {
    const int row = blockIdx.x, mat = blockIdx.y;
    const int typ = mat / 3, br = mat % 3;
    const float* W = (typ == 0 ? wq : typ == 1 ? wk : wv) + (size_t)br * 768 * 768;
    const int c = threadIdx.x * 4;
    float4 v = *(const float4*)&W[(size_t)row * 768 + c];
    size_t o = ((size_t)mat * 768 + row) * 768 + c;
    uint32_t h0 = packf16(v.x, v.y), h1 = packf16(v.z, v.w);
    *(uint32_t*)&g_Wh[o]     = h0;
    *(uint32_t*)&g_Wh[o + 2] = h1;
    if (typ < 2) {
        *(uint32_t*)&g_Wl[o]     = packf16l(v.x, v.y, h0);
        *(uint32_t*)&g_Wl[o + 2] = packf16l(v.z, v.w, h1);
    }
}

// ------------------------------------------------------------------
// Kernel 2: persistent projection GEMM, fp16, cp.async 2-stage,
// K-chunk 64, warp tile 64x32 (2x4 warp grid, min smem reads).
// A = fp16 x (1 plane). Q/K: 2 passes (W hi + W lo). V: 1 pass.
// ------------------------------------------------------------------
#define P_PLANE 9216                 // 128*72 halfs per plane (k64 + 8 pad)
#define SA_(st)     ((__half(*)[72])(ps + (st) * P_PLANE))
#define SB_(st, pl) ((__half(*)[72])(ps + (2 + (st) * 2 + (pl)) * P_PLANE))
#define P_SMEM (6 * P_PLANE * 2)     // 110592 B
#define P_TILES 3456

__global__ __launch_bounds__(256, 2) void proj_mma(
    const float* __restrict__ bq, const float* __restrict__ bk, const float* __restrict__ bv)
{
    extern __shared__ __half ps[];
    __shared__ int s_t;
    const int tid = threadIdx.x, lane = tid & 31, warp = tid >> 5;
    const int wr = warp >> 2, wc = warp & 3;         // 2x4 grid, warp tile 64x32
    const int l7 = lane & 7, l8 = lane & 8, l16 = (lane & 16) >> 1;

    for (;;) {
        __syncthreads();
        if (tid == 0) s_t = atomicAdd(&g_tickP, 1);
        __syncthreads();
        const int t = s_t;
        if (t >= P_TILES) break;
        const int rt = t & 63, rem = t >> 6;
        const int ct = rem % 6, mat = rem / 6;
        const int br = mat % 3, typ = mat / 3;

        const __half* Ap = g_x16 + ((size_t)br * 8192 + rt * 128) * 768;
        const __half* Bp[2] = {
            g_Wh + ((size_t)mat * 768 + ct * 128) * 768,
            g_Wl + ((size_t)mat * 768 + ct * 128) * 768 };

        float acc[4][4][4];                          // [mt][nt(n8)][4]
#pragma unroll
        for (int i = 0; i < 4; ++i)
#pragma unroll
            for (int j = 0; j < 4; ++j)
#pragma unroll
                for (int k = 0; k < 4; ++k) acc[i][j][k] = 0.f;

        auto load_chunk = [&](int kt, int st) {
#pragma unroll
            for (int i = 0; i < 4; ++i) {            // A: 128 rows x 8 segs
                int idx = i * 256 + tid;
                int seg = idx & 7, row = idx >> 3;
                cp16(smaddr(&SA_(st)[row][seg * 8]),
                     Ap + (size_t)row * 768 + kt * 64 + seg * 8);
            }
            const int nb = (typ == 2) ? 4 : 8;       // B: 1 or 2 planes
            for (int i = 0; i < nb; ++i) {
                int idx = i * 256 + tid;
                int seg = idx & 7, row = (idx >> 3) & 127, pl = idx >> 10;
                cp16(smaddr(&SB_(st, pl)[row][seg * 8]),
                     Bp[pl] + (size_t)row * 768 + kt * 64 + seg * 8);
            }
        };

        load_chunk(0, 0); cp_commit();

        for (int kt = 0; kt < 12; ++kt) {
            const int st = kt & 1;
            cp_wait0();
            __syncthreads();                 // releases compute(kt); proves kt-1 done
            if (kt < 11) { load_chunk(kt + 1, st ^ 1); cp_commit(); }

            __half (*sA)[72]  = SA_(st);
            __half (*sBh)[72] = SB_(st, 0), (*sBl)[72] = SB_(st, 1);
#pragma unroll
            for (int ks = 0; ks < 4; ++ks) {
                const int k0 = ks * 16;
                uint32_t ah[4][4];
#pragma unroll
                for (int mt = 0; mt < 4; ++mt)
                    ldsm4(ah[mt], smaddr(&sA[wr * 64 + mt * 16 + l7 + l8][k0 + l16]));
                uint32_t bh[2][4];
#pragma unroll
                for (int p = 0; p < 2; ++p)
                    ldsm4(bh[p], smaddr(&sBh[wc * 32 + p * 16 + l7 + l16][k0 + l8]));
#pragma unroll
                for (int p = 0; p < 2; ++p)
#pragma unroll
                    for (int mt = 0; mt < 4; ++mt) {
                        mma16h(acc[mt][2 * p],     ah[mt], bh[p]);
                        mma16h(acc[mt][2 * p + 1], ah[mt], bh[p] + 2);
                    }
                if (typ < 2) {
                    uint32_t bl[2][4];
#pragma unroll
                    for (int p = 0; p < 2; ++p)
                        ldsm4(bl[p], smaddr(&sBl[wc * 32 + p * 16 + l7 + l16][k0 + l8]));
#pragma unroll
                    for (int p = 0; p < 2; ++p)
#pragma unroll
                        for (int mt = 0; mt < 4; ++mt) {
                            mma16h(acc[mt][2 * p],     ah[mt], bl[p]);
                            mma16h(acc[mt][2 * p + 1], ah[mt], bl[p] + 2);
                        }
                }
            }
        }

        // epilogue: bias, emit fp16 planes [br][b][h][n][64].
        const float* Bb = (typ == 0 ? bq : typ == 1 ? bk : bv) + br * 768;
        __half* dh = (typ == 0 ? g_Qh : typ == 1 ? g_Kh : g_V);
        __half* dl = (typ == 0 ? g_Ql : g_Kl);
        const float qs = (typ == 0) ? LOG2E : 1.0f;
        const int tg = lane & 3, g = lane >> 2;
#pragma unroll
        for (int mt = 0; mt < 4; ++mt) {
            int R = rt * 128 + wr * 64 + mt * 16 + g;
            int b = R >> 10, n = R & 1023;
#pragma unroll
            for (int nt = 0; nt < 4; ++nt) {
                int C = ct * 128 + wc * 32 + nt * 8 + tg * 2;
                int h = C >> 6, d = C & 63;
                float2 bi = *(const float2*)&Bb[C];
                float v0 = (acc[mt][nt][0] + bi.x) * qs, v1 = (acc[mt][nt][1] + bi.y) * qs;
                float v2 = (acc[mt][nt][2] + bi.x) * qs, v3 = (acc[mt][nt][3] + bi.y) * qs;
                size_t base = (((size_t)(br * 8 + b) * 12 + h) * 1024 + n) * 64 + d;
                uint32_t h0 = packf16(v0, v1), h1 = packf16(v2, v3);
                *(uint32_t*)&dh[base]          = h0;
                *(uint32_t*)&dh[base + 8 * 64] = h1;
                if (typ < 2) {
                    *(uint32_t*)&dl[base]          = packf16l(v0, v1, h0);
                    *(uint32_t*)&dl[base + 8 * 64] = packf16l(v2, v3, h1);
                }
            }
        }
    }
}

// ------------------------------------------------------------------
// Kernel 3: persistent flash attention, fp16, ex2 softmax.
// Ticket = (brn, qt, h, bb). Row-sum l accumulated on the tensor pipe
// via ones-vector mma (no fp32 adds / shuffle reductions).
// ------------------------------------------------------------------
#define AQ_PLANE 9216                // 128*72 halfs
#define AKV_PLANE 4608               // 64*72 halfs
#define SKV_(st, pl) ((__half(*)[72])(as_ + 2 * AQ_PLANE + ((st) * 3 + (pl)) * AKV_PLANE))
#define A_SMEM ((2 * AQ_PLANE + 6 * AKV_PLANE) * 2)   // 92160 B
#define A_TILES 2304

__global__ __launch_bounds__(256, 2) void attn_kernel(float* __restrict__ out) {
    extern __shared__ __half as_[];
    __shared__ int s_t, s_c;
    __half (*sQh)[72] = (__half(*)[72])(as_);
    __half (*sQl)[72] = (__half(*)[72])(as_ + AQ_PLANE);

    const int tid = threadIdx.x, lane = tid & 31, warp = tid >> 5;
    const int g = lane >> 2, tg = lane & 3;
    const int l7 = lane & 7, l8 = lane & 8, l16 = (lane & 16) >> 1;
    const int r0 = warp * 16 + g;
    const uint32_t ones2[2] = { 0x3C003C00u, 0x3C003C00u };

    for (;;) {
        __syncthreads();
        if (tid == 0) s_t = atomicAdd(&g_tickA, 1);
        __syncthreads();
        const int t = s_t;
        if (t >= A_TILES) break;
        const int qt = t & 7, h = (t >> 3) % 12;
        const int r2 = t / 96, bb = r2 & 7, brn = r2 >> 3;
        const int tileid = (bb * 12 + h) * 8 + qt;

        const size_t hb = (((size_t)brn * 8 + bb) * 12 + h) * (size_t)(1024 * 64);
        const __half* KVp[3] = { g_Kh + hb, g_Kl + hb, g_V + hb };
        const __half* Qp[2]  = { g_Qh + hb + (size_t)qt * 128 * 64,
                                 g_Ql + hb + (size_t)qt * 128 * 64 };

        auto loadKV = [&](int jt, int st) {
#pragma unroll
            for (int i = 0; i < 6; ++i) {
                int idx = i * 256 + tid;
                int seg = idx & 7, row = (idx >> 3) & 63, pl = idx >> 9;
                cp16(smaddr(&SKV_(st, pl)[row][seg * 8]),
                     KVp[pl] + (size_t)(jt * 64 + row) * 64 + seg * 8);
            }
        };

#pragma unroll
        for (int i = 0; i < 8; ++i) {
            int idx = i * 256 + tid;
            int seg = idx & 7, row = (idx >> 3) & 127, pl = idx >> 10;
            cp16(smaddr(&(pl ? sQl : sQh)[row][seg * 8]),
                 Qp[pl] + (size_t)row * 64 + seg * 8);
        }
        loadKV(0, 0);
        cp_commit();

        float m0 = -1e30f, m1 = -1e30f;
        float lac[4] = { 0.f, 0.f, 0.f, 0.f };
        float oa[8][4];
#pragma unroll
        for (int i = 0; i < 8; ++i)
#pragma unroll
            for (int j = 0; j < 4; ++j) oa[i][j] = 0.f;

        for (int jt = 0; jt < 16; ++jt) {
            const int st = jt & 1;
            cp_wait0();
            __syncthreads();                 // releases compute(jt); proves jt-1 done
            if (jt < 15) { loadKV(jt + 1, st ^ 1); cp_commit(); }

            __half (*sKh)[72] = SKV_(st, 0), (*sKl)[72] = SKV_(st, 1);
            __half (*sV)[72]  = SKV_(st, 2);

            // ---- S = Q K^T (log2 domain) : fp16 hi/lo, 3 passes ----
            float sf[8][4];
#pragma unroll
            for (int i = 0; i < 8; ++i)
#pragma unroll
                for (int j = 0; j < 4; ++j) sf[i][j] = 0.f;
#pragma unroll
            for (int ks = 0; ks < 4; ++ks) {
                const int k0 = ks * 16;
                uint32_t qh[4], ql[4];
                ldsm4(qh, smaddr(&sQh[warp * 16 + l7 + l8][k0 + l16]));
                ldsm4(ql, smaddr(&sQl[warp * 16 + l7 + l8][k0 + l16]));
                uint32_t kh_[4][4], kl_[4][4];
#pragma unroll
                for (int p = 0; p < 4; ++p) {
                    int n0 = p * 16 + l7 + l16;
                    ldsm4(kh_[p], smaddr(&sKh[n0][k0 + l8]));
                    ldsm4(kl_[p], smaddr(&sKl[n0][k0 + l8]));
                }
#pragma unroll
                for (int p = 0; p < 4; ++p) {
                    mma16h(sf[2 * p],     qh, kh_[p]);
                    mma16h(sf[2 * p + 1], qh, kh_[p] + 2);
                }
#pragma unroll
                for (int p = 0; p < 4; ++p) {
                    mma16h(sf[2 * p],     qh, kl_[p]);
                    mma16h(sf[2 * p + 1], qh, kl_[p] + 2);
                }
#pragma unroll
                for (int p = 0; p < 4; ++p) {
                    mma16h(sf[2 * p],     ql, kh_[p]);
                    mma16h(sf[2 * p + 1], ql, kh_[p] + 2);
                }
            }

            // ---- online softmax (base-2); l handled by ones-mma ----
            float t0 = -1e30f, t1 = -1e30f;
#pragma unroll
            for (int nt = 0; nt < 8; ++nt) {
                t0 = fmaxf(t0, fmaxf(sf[nt][0], sf[nt][1]));
                t1 = fmaxf(t1, fmaxf(sf[nt][2], sf[nt][3]));
            }
            t0 = fmaxf(t0, __shfl_xor_sync(0xffffffffu, t0, 1));
            t0 = fmaxf(t0, __shfl_xor_sync(0xffffffffu, t0, 2));
            t1 = fmaxf(t1, __shfl_xor_sync(0xffffffffu, t1, 1));
            t1 = fmaxf(t1, __shfl_xor_sync(0xffffffffu, t1, 2));
            float mn0 = fmaxf(m0, t0), mn1 = fmaxf(m1, t1);
            float a0 = ex2(m0 - mn0), a1 = ex2(m1 - mn1);
            m0 = mn0; m1 = mn1;

#pragma unroll
            for (int nt = 0; nt < 8; ++nt) {
                sf[nt][0] = ex2(sf[nt][0] - mn0);
                sf[nt][1] = ex2(sf[nt][1] - mn0);
                sf[nt][2] = ex2(sf[nt][2] - mn1);
                sf[nt][3] = ex2(sf[nt][3] - mn1);
            }
            lac[0] *= a0; lac[1] *= a0; lac[2] *= a1; lac[3] *= a1;
#pragma unroll
            for (int nt = 0; nt < 8; ++nt) {
                oa[nt][0] *= a0; oa[nt][1] *= a0;
                oa[nt][2] *= a1; oa[nt][3] *= a1;
            }

            // ---- O += P V (single fp16 pass); l += P . ones ----
#pragma unroll
            for (int ks = 0; ks < 4; ++ks) {
                uint32_t ph[4];
                ph[0] = packf16(sf[2 * ks][0],     sf[2 * ks][1]);
                ph[1] = packf16(sf[2 * ks][2],     sf[2 * ks][3]);
                ph[2] = packf16(sf[2 * ks + 1][0], sf[2 * ks + 1][1]);
                ph[3] = packf16(sf[2 * ks + 1][2], sf[2 * ks + 1][3]);
                mma16h(lac, ph, ones2);
                const int kv0 = ks * 16 + l7 + l8;
                uint32_t vh_[4][4];
#pragma unroll
                for (int p = 0; p < 4; ++p) {
                    int d0 = p * 16 + l16;
                    ldsm4t(vh_[p], smaddr(&sV[kv0][d0]));
                }
#pragma unroll
                for (int p = 0; p < 4; ++p) {
                    mma16h(oa[2 * p],     ph, vh_[p]);
                    mma16h(oa[2 * p + 1], ph, vh_[p] + 2);
                }
            }
        }

        // normalize branch result (all lanes hold the row sums)
        float i0 = 1.f / lac[0], i1 = 1.f / lac[2];
#pragma unroll
        for (int nt = 0; nt < 8; ++nt) {
            oa[nt][0] *= i0; oa[nt][1] *= i0;
            oa[nt][2] *= i1; oa[nt][3] *= i1;
        }

        // last-finisher combine: first two branches store partials;
        // the third sums p0+p1+p2 in fixed order and writes out.
        if (tid == 0) { __threadfence(); s_c = atomicAdd(&g_cnt[tileid], 1); }
        __syncthreads();
        const int old = s_c;
        if (old < 2) {
            float* dst = g_part[brn];
#pragma unroll
            for (int nt = 0; nt < 8; ++nt) {
                int d = nt * 8 + tg * 2;
                size_t base = ((size_t)bb * 1024 + (size_t)(qt * 128 + r0)) * 768 + h * 64 + d;
                *(float2*)&dst[base]                   = make_float2(oa[nt][0], oa[nt][1]);
                *(float2*)&dst[base + (size_t)8 * 768] = make_float2(oa[nt][2], oa[nt][3]);
            }
        } else {
            __threadfence();
            const float* pA = g_part[brn == 0 ? 1 : 0];
            const float* pB = g_part[brn == 2 ? 1 : 2];
#pragma unroll
            for (int nt = 0; nt < 8; ++nt) {
                int d = nt * 8 + tg * 2;
                size_t base = ((size_t)bb * 1024 + (size_t)(qt * 128 + r0)) * 768 + h * 64 + d;
#pragma unroll
                for (int half = 0; half < 2; ++half) {
                    size_t a = base + (size_t)half * 8 * 768;
                    float2 me = make_float2(oa[nt][2 * half], oa[nt][2 * half + 1]);
                    float2 xa = *(const float2*)&pA[a];
                    float2 xb = *(const float2*)&pB[a];
                    float2 s0 = (brn == 0) ? me : xa;
                    float2 s1 = (brn == 1) ? me : (brn == 0 ? xa : xb);
                    float2 s2 = (brn == 2) ? me : xb;
                    float2 r;
                    r.x = (s0.x + s1.x) + s2.x;
                    r.y = (s0.y + s1.y) + s2.y;
                    *(float2*)&out[a] = r;
                }
            }
        }
    }
}

// ------------------------------------------------------------------
extern "C" void kernel_launch(void* const* d_in, const int* in_sizes, int n_in,
                              void* d_out, int out_size) {
    (void)in_sizes; (void)n_in; (void)out_size;
    const float* x  = (const float*)d_in[0];
    const float* wq = (const float*)d_in[1];
    const float* bq = (const float*)d_in[2];
    const float* wk = (const float*)d_in[3];
    const float* bk = (const float*)d_in[4];
    const float* wv = (const float*)d_in[5];
    const float* bv = (const float*)d_in[6];
    float* out = (float*)d_out;

    prep_x_fused<<<8192, 192>>>(x);
    prep_w<<<dim3(768, 9), 192>>>(wq, wk, wv);

    cudaFuncSetAttribute(proj_mma, cudaFuncAttributeMaxDynamicSharedMemorySize, P_SMEM);
    proj_mma<<<NCTA, 256, P_SMEM>>>(bq, bk, bv);

    cudaFuncSetAttribute(attn_kernel, cudaFuncAttributeMaxDynamicSharedMemorySize, A_SMEM);
    attn_kernel<<<NCTA, 256, A_SMEM>>>(out);
}

// round 16
// speedup vs baseline: 1.0104x; 1.0104x over previous
#include <cuda_runtime.h>
#include <cuda_bf16.h>
#include <cuda_fp16.h>
#include <cstdint>
#include <cstddef>

#define DEVI __device__ __forceinline__
#define LOG2E 1.4426950408889634f
#define NCTA 304                     // 152 SMs x 2 CTAs

// ------------------------------------------------------------------
// Scratch (__device__ globals; allocation-free rule)
// ------------------------------------------------------------------
__device__ int g_tickP, g_tickA;
__device__ int g_cnt[768];                         // per-(qt,h,bb) branch-finish counters
__device__ float g_part[3][8ull * 1024 * 768];     // per-branch attention partials
__device__ __half g_x16[3ull * 8192 * 768];        // fp16 branch-scaled x (all GEMMs)
__device__ __half g_Wh[9ull * 768 * 768];          // W hi (fp16); mats 6-8: only plane
__device__ __half g_Wl[9ull * 768 * 768];          // W lo (fp16 residual); mats 0-5
// attention inputs: fp16. Q,K as hi+lo split; V single plane.
__device__ __half g_Qh[3ull * 8 * 12 * 1024 * 64]; // Q pre-scaled by log2(e)
__device__ __half g_Ql[3ull * 8 * 12 * 1024 * 64];
__device__ __half g_Kh[3ull * 8 * 12 * 1024 * 64];
__device__ __half g_Kl[3ull * 8 * 12 * 1024 * 64];
__device__ __half g_V [3ull * 8 * 12 * 1024 * 64];

// ------------------------------------------------------------------
// Helpers
// ------------------------------------------------------------------
DEVI uint32_t smaddr(const void* p) { return (uint32_t)__cvta_generic_to_shared(p); }

DEVI uint32_t packf16(float a, float b) {
    __half2 h = __floats2half2_rn(a, b);
    uint32_t u; memcpy(&u, &h, 4); return u;
}
DEVI uint32_t packf16l(float a, float b, uint32_t hbits) {
    __half2 h; memcpy(&h, &hbits, 4);
    float2 f = __half22float2(h);
    return packf16(a - f.x, b - f.y);
}
DEVI float ex2(float x) { float r; asm("ex2.approx.f32 %0, %1;" : "=f"(r) : "f"(x)); return r; }

DEVI void cp16(uint32_t dst, const void* src) {
    asm volatile("cp.async.cg.shared.global [%0], [%1], 16;" :: "r"(dst), "l"(src) : "memory");
}
DEVI void cp_commit() { asm volatile("cp.async.commit_group;" ::: "memory"); }
DEVI void cp_wait0()  { asm volatile("cp.async.wait_group 0;" ::: "memory"); }

DEVI void ldsm4(uint32_t r[4], uint32_t a) {
    asm volatile("ldmatrix.sync.aligned.m8n8.x4.shared.b16 {%0,%1,%2,%3}, [%4];"
                 : "=r"(r[0]), "=r"(r[1]), "=r"(r[2]), "=r"(r[3]) : "r"(a));
}
DEVI void ldsm4t(uint32_t r[4], uint32_t a) {
    asm volatile("ldmatrix.sync.aligned.m8n8.x4.trans.shared.b16 {%0,%1,%2,%3}, [%4];"
                 : "=r"(r[0]), "=r"(r[1]), "=r"(r[2]), "=r"(r[3]) : "r"(a));
}
DEVI void mma16h(float d[4], const uint32_t a[4], const uint32_t b[2]) {
    asm volatile(
        "mma.sync.aligned.m16n8k16.row.col.f32.f16.f16.f32 "
        "{%0,%1,%2,%3}, {%4,%5,%6,%7}, {%8,%9}, {%0,%1,%2,%3};"
        : "+f"(d[0]), "+f"(d[1]), "+f"(d[2]), "+f"(d[3])
        : "r"(a[0]), "r"(a[1]), "r"(a[2]), "r"(a[3]), "r"(b[0]), "r"(b[1]));
}

// ------------------------------------------------------------------
// Kernel 1: fused row scalars + branch-scaled fp16 x.
// Resets tickets and branch-finish counters (graph replay safe).
// ------------------------------------------------------------------
__global__ __launch_bounds__(192) void prep_x_fused(const float* __restrict__ x) {
    __shared__ float red[6];
    __shared__ float sbr[2];
    const int row = blockIdx.x, tid = threadIdx.x;
    if (row == 0 && tid == 0) { g_tickP = 0; g_tickA = 0; }
    if (row < 4) g_cnt[row * 192 + tid] = 0;

    float4 v = *(const float4*)&x[(size_t)row * 768 + tid * 4];
    float ss = fmaf(v.x, v.x, fmaf(v.y, v.y, fmaf(v.z, v.z, v.w * v.w)));
#pragma unroll
    for (int o = 16; o; o >>= 1) ss += __shfl_xor_sync(0xffffffffu, ss, o);
    if ((tid & 31) == 0) red[tid >> 5] = ss;
    __syncthreads();
    if (tid == 0) {
        float t = 0.f;
#pragma unroll
        for (int i = 0; i < 6; ++i) t += red[i];
        float n = fmaxf(sqrtf(t), 1e-5f);
        const float sc = 0.316227766016837933f;     // sqrt(0.1)
        float a = sc * n;
        float th = tanhf(a);
        float s_pre = th / a;
        float norm_h = th / sc;
        float maxn = (1.0f - 4e-3f) / sc;
        sbr[0] = (norm_h > maxn) ? s_pre * (maxn / norm_h) : s_pre;
        float arg = fminf(a, 1.0f - 1e-5f);
        float art = 0.5f * logf((1.0f + arg) / (1.0f - arg));
        sbr[1] = art / (n * sc);
    }
    __syncthreads();
    {
        const int c = tid * 4;
#pragma unroll
        for (int br = 0; br < 3; ++br) {
            float s = (br == 0) ? 1.0f : sbr[br - 1];
            size_t o = ((size_t)br * 8192 + row) * 768 + c;
            *(uint32_t*)&g_x16[o]     = packf16(v.x * s, v.y * s);
            *(uint32_t*)&g_x16[o + 2] = packf16(v.z * s, v.w * s);
        }
    }
}

// ------------------------------------------------------------------
// Kernel 1c: split weights into fp16 hi(+lo) planes.
// ------------------------------------------------------------------
__global__ __launch_bounds__(192) void prep_w(
    const float* __restrict__ wq, const float* __restrict__ wk, const float* __restrict__ wv) {
    const int row = blockIdx.x, mat = blockIdx.y;
    const int typ = mat / 3, br = mat % 3;
    const float* W = (typ == 0 ? wq : typ == 1 ? wk : wv) + (size_t)br * 768 * 768;
    const int c = threadIdx.x * 4;
    float4 v = *(const float4*)&W[(size_t)row * 768 + c];
    size_t o = ((size_t)mat * 768 + row) * 768 + c;
    uint32_t h0 = packf16(v.x, v.y), h1 = packf16(v.z, v.w);
    *(uint32_t*)&g_Wh[o]     = h0;
    *(uint32_t*)&g_Wh[o + 2] = h1;
    if (typ < 2) {
        *(uint32_t*)&g_Wl[o]     = packf16l(v.x, v.y, h0);
        *(uint32_t*)&g_Wl[o + 2] = packf16l(v.z, v.w, h1);
    }
}

// ------------------------------------------------------------------
// Kernel 2: persistent projection GEMM, fp16, cp.async 2-stage,
// K-chunk 64 (12 chunks, 1 barrier each). Warp tile 32x64 (R14).
// A = fp16 x (1 plane). Q/K: 2 passes (W hi + W lo). V: 1 pass.
// ------------------------------------------------------------------
#define P_PLANE 9216                 // 128*72 halfs per plane (k64 + 8 pad)
#define SA_(st)     ((__half(*)[72])(ps + (st) * P_PLANE))
#define SB_(st, pl) ((__half(*)[72])(ps + (2 + (st) * 2 + (pl)) * P_PLANE))
#define P_SMEM (6 * P_PLANE * 2)     // 110592 B
#define P_TILES 3456

__global__ __launch_bounds__(256, 2) void proj_mma(
    const float* __restrict__ bq, const float* __restrict__ bk, const float* __restrict__ bv)
{
    extern __shared__ __half ps[];
    __shared__ int s_t[2];
    const int tid = threadIdx.x, lane = tid & 31, warp = tid >> 5;
    const int wr = warp >> 1, wc = warp & 1;
    const int l7 = lane & 7, l8 = lane & 8, l16 = (lane & 16) >> 1;

    for (int it = 0;; ++it) {
        if (tid == 0) s_t[it & 1] = atomicAdd(&g_tickP, 1);
        __syncthreads();                 // publishes s_t; also fences smem reuse
        const int t = s_t[it & 1];
        if (t >= P_TILES) break;
        const int rt = t & 63, rem = t >> 6;
        const int ct = rem % 6, mat = rem / 6;
        const int br = mat % 3, typ = mat / 3;

        const __half* Ap = g_x16 + ((size_t)br * 8192 + rt * 128) * 768;
        const __half* Bp[2] = {
            g_Wh + ((size_t)mat * 768 + ct * 128) * 768,
            g_Wl + ((size_t)mat * 768 + ct * 128) * 768 };

        float acc[2][8][4];
#pragma unroll
        for (int i = 0; i < 2; ++i)
#pragma unroll
            for (int j = 0; j < 8; ++j)
#pragma unroll
                for (int k = 0; k < 4; ++k) acc[i][j][k] = 0.f;

        auto load_chunk = [&](int kt, int st) {
#pragma unroll
            for (int i = 0; i < 4; ++i) {            // A: 128 rows x 8 segs
                int idx = i * 256 + tid;
                int seg = idx & 7, row = idx >> 3;
                cp16(smaddr(&SA_(st)[row][seg * 8]),
                     Ap + (size_t)row * 768 + kt * 64 + seg * 8);
            }
            const int nb = (typ == 2) ? 4 : 8;       // B: 1 or 2 planes
            for (int i = 0; i < nb; ++i) {
                int idx = i * 256 + tid;
                int seg = idx & 7, row = (idx >> 3) & 127, pl = idx >> 10;
                cp16(smaddr(&SB_(st, pl)[row][seg * 8]),
                     Bp[pl] + (size_t)row * 768 + kt * 64 + seg * 8);
            }
        };

        load_chunk(0, 0); cp_commit();

        for (int kt = 0; kt < 12; ++kt) {
            const int st = kt & 1;
            cp_wait0();
            __syncthreads();                 // releases compute(kt); proves kt-1 done
            if (kt < 11) { load_chunk(kt + 1, st ^ 1); cp_commit(); }

            __half (*sA)[72]  = SA_(st);
            __half (*sBh)[72] = SB_(st, 0), (*sBl)[72] = SB_(st, 1);
#pragma unroll
            for (int ks = 0; ks < 4; ++ks) {
                const int k0 = ks * 16;
                uint32_t ah[2][4];
#pragma unroll
                for (int mt = 0; mt < 2; ++mt)
                    ldsm4(ah[mt], smaddr(&sA[wr * 32 + mt * 16 + l7 + l8][k0 + l16]));
                uint32_t bh[4][4];
#pragma unroll
                for (int p = 0; p < 4; ++p)
                    ldsm4(bh[p], smaddr(&sBh[wc * 64 + p * 16 + l7 + l16][k0 + l8]));
#pragma unroll
                for (int p = 0; p < 4; ++p)
#pragma unroll
                    for (int mt = 0; mt < 2; ++mt) {
                        mma16h(acc[mt][2 * p],     ah[mt], bh[p]);
                        mma16h(acc[mt][2 * p + 1], ah[mt], bh[p] + 2);
                    }
                if (typ < 2) {
                    uint32_t bl[4][4];
#pragma unroll
                    for (int p = 0; p < 4; ++p)
                        ldsm4(bl[p], smaddr(&sBl[wc * 64 + p * 16 + l7 + l16][k0 + l8]));
#pragma unroll
                    for (int p = 0; p < 4; ++p)
#pragma unroll
                        for (int mt = 0; mt < 2; ++mt) {
                            mma16h(acc[mt][2 * p],     ah[mt], bl[p]);
                            mma16h(acc[mt][2 * p + 1], ah[mt], bl[p] + 2);
                        }
                }
            }
        }

        // epilogue: bias, emit fp16 planes [br][b][h][n][64].
        const float* Bb = (typ == 0 ? bq : typ == 1 ? bk : bv) + br * 768;
        __half* dh = (typ == 0 ? g_Qh : typ == 1 ? g_Kh : g_V);
        __half* dl = (typ == 0 ? g_Ql : g_Kl);
        const float qs = (typ == 0) ? LOG2E : 1.0f;
        const int h  = ct * 2 + wc;
        const int bb = (rt * 128) >> 10;
        const int nb = (rt * 128) & 1023;
        const int tg = lane & 3, g = lane >> 2;
#pragma unroll
        for (int mt = 0; mt < 2; ++mt) {
            int r = wr * 32 + mt * 16 + g;
#pragma unroll
            for (int nt = 0; nt < 8; ++nt) {
                int d = nt * 8 + tg * 2;
                float2 bi = *(const float2*)&Bb[h * 64 + d];
                float v0 = (acc[mt][nt][0] + bi.x) * qs, v1 = (acc[mt][nt][1] + bi.y) * qs;
                float v2 = (acc[mt][nt][2] + bi.x) * qs, v3 = (acc[mt][nt][3] + bi.y) * qs;
                size_t base = ((((size_t)br * 8 + bb) * 12 + h) * 1024 + (nb + r)) * 64 + d;
                uint32_t h0 = packf16(v0, v1), h1 = packf16(v2, v3);
                *(uint32_t*)&dh[base]          = h0;
                *(uint32_t*)&dh[base + 8 * 64] = h1;
                if (typ < 2) {
                    *(uint32_t*)&dl[base]          = packf16l(v0, v1, h0);
                    *(uint32_t*)&dl[base + 8 * 64] = packf16l(v2, v3, h1);
                }
            }
        }
        __syncthreads();                 // all reads of s_t/smem done before next ticket
    }
}

// ------------------------------------------------------------------
// Kernel 3: persistent flash attention, fp16, ex2 softmax (R14 math).
// Ticket = (brn, qt, h, bb). Single barrier per KV tile.
// Cross-branch sum via last-finisher (fixed-order, deterministic).
// ------------------------------------------------------------------
#define AQ_PLANE 9216                // 128*72 halfs
#define AKV_PLANE 4608               // 64*72 halfs
#define SKV_(st, pl) ((__half(*)[72])(as_ + 2 * AQ_PLANE + ((st) * 3 + (pl)) * AKV_PLANE))
#define A_SMEM ((2 * AQ_PLANE + 6 * AKV_PLANE) * 2)   // 92160 B
#define A_TILES 2304

__global__ __launch_bounds__(256, 2) void attn_kernel(float* __restrict__ out) {
    extern __shared__ __half as_[];
    __shared__ int s_t[2];
    __shared__ int s_c;
    __half (*sQh)[72] = (__half(*)[72])(as_);
    __half (*sQl)[72] = (__half(*)[72])(as_ + AQ_PLANE);

    const int tid = threadIdx.x, lane = tid & 31, warp = tid >> 5;
    const int g = lane >> 2, tg = lane & 3;
    const int l7 = lane & 7, l8 = lane & 8, l16 = (lane & 16) >> 1;
    const int r0 = warp * 16 + g;

    for (int it = 0;; ++it) {
        if (tid == 0) s_t[it & 1] = atomicAdd(&g_tickA, 1);
        __syncthreads();
        const int t = s_t[it & 1];
        if (t >= A_TILES) break;
        const int qt = t & 7, h = (t >> 3) % 12;
        const int r2 = t / 96, bb = r2 & 7, brn = r2 >> 3;
        const int tileid = (bb * 12 + h) * 8 + qt;

        const size_t hb = (((size_t)brn * 8 + bb) * 12 + h) * (size_t)(1024 * 64);
        const __half* KVp[3] = { g_Kh + hb, g_Kl + hb, g_V + hb };
        const __half* Qp[2]  = { g_Qh + hb + (size_t)qt * 128 * 64,
                                 g_Ql + hb + (size_t)qt * 128 * 64 };

        auto loadKV = [&](int jt, int st) {
#pragma unroll
            for (int i = 0; i < 6; ++i) {
                int idx = i * 256 + tid;
                int seg = idx & 7, row = (idx >> 3) & 63, pl = idx >> 9;
                cp16(smaddr(&SKV_(st, pl)[row][seg * 8]),
                     KVp[pl] + (size_t)(jt * 64 + row) * 64 + seg * 8);
            }
        };

#pragma unroll
        for (int i = 0; i < 8; ++i) {
            int idx = i * 256 + tid;
            int seg = idx & 7, row = (idx >> 3) & 127, pl = idx >> 10;
            cp16(smaddr(&(pl ? sQl : sQh)[row][seg * 8]),
                 Qp[pl] + (size_t)row * 64 + seg * 8);
        }
        loadKV(0, 0);
        cp_commit();

        float m0 = -1e30f, m1 = -1e30f, l0 = 0.f, l1 = 0.f;
        float oa[8][4];
#pragma unroll
        for (int i = 0; i < 8; ++i)
#pragma unroll
            for (int j = 0; j < 4; ++j) oa[i][j] = 0.f;

        for (int jt = 0; jt < 16; ++jt) {
            const int st = jt & 1;
            cp_wait0();
            __syncthreads();                 // releases compute(jt); proves jt-1 done
            if (jt < 15) { loadKV(jt + 1, st ^ 1); cp_commit(); }

            __half (*sKh)[72] = SKV_(st, 0), (*sKl)[72] = SKV_(st, 1);
            __half (*sV)[72]  = SKV_(st, 2);

            // ---- S = Q K^T (log2 domain) : fp16 hi/lo, 3 passes ----
            float sf[8][4];
#pragma unroll
            for (int i = 0; i < 8; ++i)
#pragma unroll
                for (int j = 0; j < 4; ++j) sf[i][j] = 0.f;
#pragma unroll
            for (int ks = 0; ks < 4; ++ks) {
                const int k0 = ks * 16;
                uint32_t qh[4], ql[4];
                ldsm4(qh, smaddr(&sQh[warp * 16 + l7 + l8][k0 + l16]));
                ldsm4(ql, smaddr(&sQl[warp * 16 + l7 + l8][k0 + l16]));
                uint32_t kh_[4][4], kl_[4][4];
#pragma unroll
                for (int p = 0; p < 4; ++p) {
                    int n0 = p * 16 + l7 + l16;
                    ldsm4(kh_[p], smaddr(&sKh[n0][k0 + l8]));
                    ldsm4(kl_[p], smaddr(&sKl[n0][k0 + l8]));
                }
#pragma unroll
                for (int p = 0; p < 4; ++p) {
                    mma16h(sf[2 * p],     qh, kh_[p]);
                    mma16h(sf[2 * p + 1], qh, kh_[p] + 2);
                }
#pragma unroll
                for (int p = 0; p < 4; ++p) {
                    mma16h(sf[2 * p],     qh, kl_[p]);
                    mma16h(sf[2 * p + 1], qh, kl_[p] + 2);
                }
#pragma unroll
                for (int p = 0; p < 4; ++p) {
                    mma16h(sf[2 * p],     ql, kh_[p]);
                    mma16h(sf[2 * p + 1], ql, kh_[p] + 2);
                }
            }

            // ---- online softmax (base-2) ----
            float t0 = -1e30f, t1 = -1e30f;
#pragma unroll
            for (int nt = 0; nt < 8; ++nt) {
                t0 = fmaxf(t0, fmaxf(sf[nt][0], sf[nt][1]));
                t1 = fmaxf(t1, fmaxf(sf[nt][2], sf[nt][3]));
            }
            t0 = fmaxf(t0, __shfl_xor_sync(0xffffffffu, t0, 1));
            t0 = fmaxf(t0, __shfl_xor_sync(0xffffffffu, t0, 2));
            t1 = fmaxf(t1, __shfl_xor_sync(0xffffffffu, t1, 1));
            t1 = fmaxf(t1, __shfl_xor_sync(0xffffffffu, t1, 2));
            float mn0 = fmaxf(m0, t0), mn1 = fmaxf(m1, t1);
            float a0 = ex2(m0 - mn0), a1 = ex2(m1 - mn1);
            m0 = mn0; m1 = mn1;

            float rs0 = 0.f, rs1 = 0.f;
#pragma unroll
            for (int nt = 0; nt < 8; ++nt) {
                sf[nt][0] = ex2(sf[nt][0] - mn0);
                sf[nt][1] = ex2(sf[nt][1] - mn0);
                sf[nt][2] = ex2(sf[nt][2] - mn1);
                sf[nt][3] = ex2(sf[nt][3] - mn1);
                rs0 += sf[nt][0] + sf[nt][1];
                rs1 += sf[nt][2] + sf[nt][3];
            }
            l0 = l0 * a0 + rs0;
            l1 = l1 * a1 + rs1;
#pragma unroll
            for (int nt = 0; nt < 8; ++nt) {
                oa[nt][0] *= a0; oa[nt][1] *= a0;
                oa[nt][2] *= a1; oa[nt][3] *= a1;
            }

            // ---- O += P V : fp16 single pass ----
#pragma unroll
            for (int ks = 0; ks < 4; ++ks) {
                uint32_t ph[4];
                ph[0] = packf16(sf[2 * ks][0],     sf[2 * ks][1]);
                ph[1] = packf16(sf[2 * ks][2],     sf[2 * ks][3]);
                ph[2] = packf16(sf[2 * ks + 1][0], sf[2 * ks + 1][1]);
                ph[3] = packf16(sf[2 * ks + 1][2], sf[2 * ks + 1][3]);
                const int kv0 = ks * 16 + l7 + l8;
                uint32_t vh_[4][4];
#pragma unroll
                for (int p = 0; p < 4; ++p) {
                    int d0 = p * 16 + l16;
                    ldsm4t(vh_[p], smaddr(&sV[kv0][d0]));
                }
#pragma unroll
                for (int p = 0; p < 4; ++p) {
                    mma16h(oa[2 * p],     ph, vh_[p]);
                    mma16h(oa[2 * p + 1], ph, vh_[p] + 2);
                }
            }
        }

        // normalize branch result
        float L0 = l0 + __shfl_xor_sync(0xffffffffu, l0, 1);
        L0 += __shfl_xor_sync(0xffffffffu, L0, 2);
        float L1 = l1 + __shfl_xor_sync(0xffffffffu, l1, 1);
        L1 += __shfl_xor_sync(0xffffffffu, L1, 2);
        float i0 = 1.f / L0, i1 = 1.f / L1;
#pragma unroll
        for (int nt = 0; nt < 8; ++nt) {
            oa[nt][0] *= i0; oa[nt][1] *= i0;
            oa[nt][2] *= i1; oa[nt][3] *= i1;
        }

        // last-finisher combine: first two branches store partials;
        // the third sums p0+p1+p2 in fixed order and writes out.
        if (tid == 0) { __threadfence(); s_c = atomicAdd(&g_cnt[tileid], 1); }
        __syncthreads();
        const int old = s_c;
        if (old < 2) {
            float* dst = g_part[brn];
#pragma unroll
            for (int nt = 0; nt < 8; ++nt) {
                int d = nt * 8 + tg * 2;
                size_t base = ((size_t)bb * 1024 + (size_t)(qt * 128 + r0)) * 768 + h * 64 + d;
                *(float2*)&dst[base]                   = make_float2(oa[nt][0], oa[nt][1]);
                *(float2*)&dst[base + (size_t)8 * 768] = make_float2(oa[nt][2], oa[nt][3]);
            }
        } else {
            __threadfence();
            const float* pA = g_part[brn == 0 ? 1 : 0];
            const float* pB = g_part[brn == 2 ? 1 : 2];
#pragma unroll
            for (int nt = 0; nt < 8; ++nt) {
                int d = nt * 8 + tg * 2;
                size_t base = ((size_t)bb * 1024 + (size_t)(qt * 128 + r0)) * 768 + h * 64 + d;
#pragma unroll
                for (int half = 0; half < 2; ++half) {
                    size_t a = base + (size_t)half * 8 * 768;
                    float2 me = make_float2(oa[nt][2 * half], oa[nt][2 * half + 1]);
                    float2 xa = *(const float2*)&pA[a];
                    float2 xb = *(const float2*)&pB[a];
                    float2 s0 = (brn == 0) ? me : xa;
                    float2 s1 = (brn == 1) ? me : (brn == 0 ? xa : xb);
                    float2 s2 = (brn == 2) ? me : xb;
                    float2 r;
                    r.x = (s0.x + s1.x) + s2.x;
                    r.y = (s0.y + s1.y) + s2.y;
                    *(float2*)&out[a] = r;
                }
            }
        }
        __syncthreads();                 // s_c / smem reuse fence before next ticket
    }
}

// ------------------------------------------------------------------
extern "C" void kernel_launch(void* const* d_in, const int* in_sizes, int n_in,
                              void* d_out, int out_size) {
    (void)in_sizes; (void)n_in; (void)out_size;
    const float* x  = (const float*)d_in[0];
    const float* wq = (const float*)d_in[1];
    const float* bq = (const float*)d_in[2];
    const float* wk = (const float*)d_in[3];
    const float* bk = (const float*)d_in[4];
    const float* wv = (const float*)d_in[5];
    const float* bv = (const float*)d_in[6];
    float* out = (float*)d_out;

    prep_x_fused<<<8192, 192>>>(x);
    prep_w<<<dim3(768, 9), 192>>>(wq, wk, wv);

    cudaFuncSetAttribute(proj_mma, cudaFuncAttributeMaxDynamicSharedMemorySize, P_SMEM);
    proj_mma<<<NCTA, 256, P_SMEM>>>(bq, bk, bv);

    cudaFuncSetAttribute(attn_kernel, cudaFuncAttributeMaxDynamicSharedMemorySize, A_SMEM);
    attn_kernel<<<NCTA, 256, A_SMEM>>>(out);
}